// round 8
// baseline (speedup 1.0000x reference)
#include <cuda_runtime.h>
#include <cstdint>
#include <cstddef>

#define DI __device__ __forceinline__
static const int D_DIM = 512;
#define MAXN 32768
#define MAXK 1024
#define NBN  8

extern "C" __device__ float __nv_logf(float);

// Scratch (device globals; no allocation allowed)
__device__ float g_xT[(size_t)D_DIM * MAXN];   // 64MB transposed combined input [d][m]
__device__ float g_cT[(size_t)D_DIM * MAXK];   //  2MB transposed normalized codebook [d][k]
__device__ float g_pm[(size_t)MAXN * NBN];
__device__ int   g_pi[(size_t)MAXN * NBN];
__device__ float g_ps[(size_t)MAXN * NBN];

// ---------------------------------------------------------------------------
// Threefry-2x32 (exact JAX, partitionable mode)
// ---------------------------------------------------------------------------
__host__ __device__ inline uint32_t rotl32(uint32_t x, int r) {
    return (x << r) | (x >> (32 - r));
}
__host__ __device__ inline void threefry2x32(uint32_t k0, uint32_t k1,
                                             uint32_t& x0, uint32_t& x1) {
    uint32_t k2 = k0 ^ k1 ^ 0x1BD11BDAu;
    x0 += k0; x1 += k1;
#define TFR(r) { x0 += x1; x1 = rotl32(x1, r); x1 ^= x0; }
    TFR(13) TFR(15) TFR(26) TFR(6)
    x0 += k1; x1 += k2 + 1u;
    TFR(17) TFR(29) TFR(16) TFR(24)
    x0 += k2; x1 += k0 + 2u;
    TFR(13) TFR(15) TFR(26) TFR(6)
    x0 += k0; x1 += k1 + 3u;
    TFR(17) TFR(29) TFR(16) TFR(24)
    x0 += k1; x1 += k2 + 4u;
    TFR(13) TFR(15) TFR(26) TFR(6)
    x0 += k2; x1 += k0 + 5u;
#undef TFR
}
DI uint32_t tf_bits(uint32_t k0, uint32_t k1, uint32_t i) {
    uint32_t x0 = 0u, x1 = i;
    threefry2x32(k0, k1, x0, x1);
    return x0 ^ x1;
}
#define TINYF 1.17549435e-38f

// ---------------------------------------------------------------------------
// Packed fp32x2 FMA + misc helpers
// ---------------------------------------------------------------------------
typedef unsigned long long u64;
DI u64 pk2(float lo, float hi) {
    u64 r; asm("mov.b64 %0, {%1,%2};" : "=l"(r) : "f"(lo), "f"(hi)); return r;
}
DI void upk2(u64 p, float& lo, float& hi) {
    asm("mov.b64 {%0,%1}, %2;" : "=f"(lo), "=f"(hi) : "l"(p));
}
DI u64 fma2(u64 a, u64 b, u64 c) {
    u64 d; asm("fma.rn.f32x2 %0, %1, %2, %3;" : "=l"(d) : "l"(a), "l"(b), "l"(c));
    return d;
}
DI uint32_t smem_u32(const void* p) {
    uint32_t a;
    asm("{ .reg .u64 t; cvta.to.shared.u64 t, %1; cvt.u32.u64 %0, t; }"
        : "=r"(a) : "l"(p));
    return a;
}
DI void cp16(uint32_t saddr, const void* g) {
    asm volatile("cp.async.cg.shared.global [%0], [%1], 16;"
                 :: "r"(saddr), "l"(g) : "memory");
}
#define CP_COMMIT() asm volatile("cp.async.commit_group;" ::: "memory")
#define CP_WAIT1()  asm volatile("cp.async.wait_group 1;" ::: "memory")
#define CP_WAIT0()  asm volatile("cp.async.wait_group 0;" ::: "memory")
DI void lds128(float* r, uint32_t addr) {
    asm volatile("ld.shared.v4.f32 {%0,%1,%2,%3}, [%4];"
        : "=f"(r[0]), "=f"(r[1]), "=f"(r[2]), "=f"(r[3]) : "r"(addr));
}
DI void lds_2x64(u64& r0, u64& r1, uint32_t addr) {
    asm volatile("ld.shared.v2.b64 {%0,%1}, [%2];"
        : "=l"(r0), "=l"(r1) : "r"(addr));
}
DI void barx(int id, int n) {
    asm volatile("bar.sync %0, %1;" :: "r"(id), "r"(n) : "memory");
}

// ---------------------------------------------------------------------------
// Kernel 1: codebook: normalize rows, write TRANSPOSED g_cT[d][k]
// ---------------------------------------------------------------------------
__global__ __launch_bounds__(256) void norm_cb_T(const float* __restrict__ cb) {
    __shared__ float sx[16][529];
    int t = threadIdx.x, lane = t & 31, w = t >> 5;
    int k0 = blockIdx.x * 16;
#pragma unroll
    for (int rr = 0; rr < 2; rr++) {
        int row = w * 2 + rr;
        const float4* rp = (const float4*)(cb + (size_t)(k0 + row) * D_DIM);
        float4 v[4]; float ss = 0.f;
#pragma unroll
        for (int i = 0; i < 4; i++) {
            v[i] = rp[lane + 32 * i];
            ss += v[i].x*v[i].x + v[i].y*v[i].y + v[i].z*v[i].z + v[i].w*v[i].w;
        }
#pragma unroll
        for (int o = 16; o; o >>= 1) ss += __shfl_xor_sync(0xffffffffu, ss, o);
        float inv = 1.0f / fmaxf(sqrtf(ss), 1e-8f);
#pragma unroll
        for (int i = 0; i < 4; i++) {
            int c = 4 * (lane + 32 * i);
            sx[row][c]     = v[i].x * inv;
            sx[row][c + 1] = v[i].y * inv;
            sx[row][c + 2] = v[i].z * inv;
            sx[row][c + 3] = v[i].w * inv;
        }
    }
    __syncthreads();
    int m = lane & 15, hw = lane >> 4;
#pragma unroll
    for (int dd = 0; dd < 32; dd++) {
        int d = w * 64 + dd * 2 + hw;
        g_cT[(size_t)d * MAXK + k0 + m] = sx[m][d];
    }
}

// ---------------------------------------------------------------------------
// Kernel 2: x = 0.5*st/||st|| + 0.5*ad/||ad||, write TRANSPOSED g_xT[d][m]
// ---------------------------------------------------------------------------
__global__ __launch_bounds__(256) void combine_T(const float* __restrict__ st,
                                                 const float* __restrict__ ad) {
    __shared__ float sx[16][529];
    int t = threadIdx.x, lane = t & 31, w = t >> 5;
    int m0 = blockIdx.x * 16;
#pragma unroll
    for (int rr = 0; rr < 2; rr++) {
        int row = w * 2 + rr;
        const float4* sp = (const float4*)(st + (size_t)(m0 + row) * D_DIM);
        const float4* ap = (const float4*)(ad + (size_t)(m0 + row) * D_DIM);
        float4 sv[4], av[4]; float ss = 0.f, aa = 0.f;
#pragma unroll
        for (int i = 0; i < 4; i++) {
            sv[i] = sp[lane + 32 * i];
            av[i] = ap[lane + 32 * i];
            ss += sv[i].x*sv[i].x + sv[i].y*sv[i].y + sv[i].z*sv[i].z + sv[i].w*sv[i].w;
            aa += av[i].x*av[i].x + av[i].y*av[i].y + av[i].z*av[i].z + av[i].w*av[i].w;
        }
#pragma unroll
        for (int o = 16; o; o >>= 1) {
            ss += __shfl_xor_sync(0xffffffffu, ss, o);
            aa += __shfl_xor_sync(0xffffffffu, aa, o);
        }
        float is = 0.5f / fmaxf(sqrtf(ss), 1e-8f);
        float ia = 0.5f / fmaxf(sqrtf(aa), 1e-8f);
#pragma unroll
        for (int i = 0; i < 4; i++) {
            int c = 4 * (lane + 32 * i);
            sx[row][c]     = sv[i].x * is + av[i].x * ia;
            sx[row][c + 1] = sv[i].y * is + av[i].y * ia;
            sx[row][c + 2] = sv[i].z * is + av[i].z * ia;
            sx[row][c + 3] = sv[i].w * is + av[i].w * ia;
        }
    }
    __syncthreads();
    int m = lane & 15, hw = lane >> 4;
#pragma unroll
    for (int dd = 0; dd < 32; dd++) {
        int d = w * 64 + dd * 2 + hw;
        g_xT[(size_t)d * MAXN + m0 + m] = sx[m][d];
    }
}

// ---------------------------------------------------------------------------
// Kernel 3: warp-specialized FFMA2 GEMM + threefry noise (conflict-free frags)
//   384 threads: t<256 GEMM (128x128 tile, BK=32, 2-stage cp.async, barrier 1),
//   t>=256 noise (4 warps: threefry + both precise logs for g1, fast log for
//   eg; results to smem float2). Join at __syncthreads, light epilogue.
//   Fragment map (thread t: ty=t>>4, tx=t&15):
//     rows i=0..7  -> bm + ty*4 + (i&3) + (i>>2)*64
//     cols ci=0..7 -> bn + tx*4 + (ci&3) + (ci>>2)*64
// SMEM floats: A [0,8192) 2 stages; B [8192,16384) 2 stages;
//              noise float2[16384] at +16384 floats. Total 192KB.
// ---------------------------------------------------------------------------
DI void issue_chunk(int c, int s, uint32_t sbase, int bm, int bn, int t) {
#pragma unroll
    for (int i = 0; i < 4; i++) {
        int u = t + i * 256;
        int kk = u >> 5, j4 = (u & 31) << 2;
        const float* ga = g_xT + (size_t)(c * 32 + kk) * MAXN + bm + j4;
        cp16(sbase + (uint32_t)(s * 4096 + kk * 128 + j4) * 4u, ga);
        const float* gb = g_cT + (size_t)(c * 32 + kk) * MAXK + bn + j4;
        cp16(sbase + (uint32_t)(8192 + s * 4096 + kk * 128 + j4) * 4u, gb);
    }
}

__global__ __launch_bounds__(384, 1) void gemm_ws(
        float* __restrict__ ws,
        uint32_t k1a, uint32_t k1b, uint32_t k2a, uint32_t k2b) {
    extern __shared__ float sm[];
    const uint32_t sbase = smem_u32(sm);
    float2* nz = (float2*)(sm + 16384);
    const int t = threadIdx.x;
    const int bn = blockIdx.x * 128, bm = blockIdx.y * 128;

    if (t < 256) {
        // ===================== GEMM role =====================
        const int lane = t & 31;
        const int tx = t & 15, ty = t >> 4;

        u64 acc[8][4];
#pragma unroll
        for (int i = 0; i < 8; i++)
#pragma unroll
            for (int j = 0; j < 4; j++) acc[i][j] = 0ull;

        issue_chunk(0, 0, sbase, bm, bn, t);
        CP_COMMIT();

        for (int c = 0; c < 16; c++) {
            if (c < 15) {
                issue_chunk(c + 1, (c + 1) & 1, sbase, bm, bn, t);
                CP_COMMIT();
                CP_WAIT1();
            } else {
                CP_WAIT0();
            }
            barx(1, 256);
            const uint32_t AS = sbase + (uint32_t)((c & 1) * 4096) * 4u;
            const uint32_t BS = sbase + (uint32_t)(8192 + (c & 1) * 4096) * 4u;
#pragma unroll
            for (int kk = 0; kk < 32; kk++) {
                // A frag: 4+4 split, broadcast within half-warp (2 addrs/warp)
                float a[8];
                lds128(a,     AS + (uint32_t)(kk * 128 + ty * 4) * 4u);
                lds128(a + 4, AS + (uint32_t)(kk * 128 + 64 + ty * 4) * 4u);
                // B frag pairs direct from smem (contiguous 16B/lane, no movs)
                u64 b2[4];
                lds_2x64(b2[0], b2[1], BS + (uint32_t)(kk * 128 + tx * 4) * 4u);
                lds_2x64(b2[2], b2[3], BS + (uint32_t)(kk * 128 + 64 + tx * 4) * 4u);
#pragma unroll
                for (int i = 0; i < 8; i++) {
                    u64 a2 = pk2(a[i], a[i]);
#pragma unroll
                    for (int j = 0; j < 4; j++)
                        acc[i][j] = fma2(a2, b2[j], acc[i][j]);
                }
            }
            barx(1, 256);
        }

        __syncthreads();   // join with noise warps (drains their STS)

        // ---- epilogue: noise fully precomputed (g1, eg) ----
#pragma unroll 1
        for (int i = 0; i < 8; i++) {
            float o[8];
#pragma unroll
            for (int j = 0; j < 4; j++) upk2(acc[i][j], o[2 * j], o[2 * j + 1]);
            int grow = bm + ty * 4 + (i & 3) + (i >> 2) * 64;
            float bmax = -3.4e38f; int bidx = 0; float bsum = 0.f;
            float p[8];
#pragma unroll
            for (int ci = 0; ci < 8; ci++) {
                float2 nv = nz[(i * 8 + ci) * 256 + t];
                float v1 = o[ci] + nv.x;
                int gcol = bn + tx * 4 + (ci & 3) + (ci >> 2) * 64;
                if (v1 > bmax) { bmax = v1; bidx = gcol; }
                p[ci] = __expf(o[ci]) * nv.y;
                bsum += p[ci];
            }
            float* wrow = ws + (size_t)grow * 1024 + bn + tx * 4;
            *(float4*)(wrow)      = make_float4(p[0], p[1], p[2], p[3]);
            *(float4*)(wrow + 64) = make_float4(p[4], p[5], p[6], p[7]);
            // reduce over the 16 tx lanes; ties: lower col index wins.
            // Within a thread cols ascend with ci except the 64-offset split:
            // all cols for tx are distinct across lanes; strict > keeps first
            // encountered, and cross-lane tie uses explicit index compare.
#pragma unroll
            for (int off = 8; off; off >>= 1) {
                float om = __shfl_xor_sync(0xffffffffu, bmax, off);
                int   oi = __shfl_xor_sync(0xffffffffu, bidx, off);
                float os = __shfl_xor_sync(0xffffffffu, bsum, off);
                if (om > bmax || (om == bmax && oi < bidx)) { bmax = om; bidx = oi; }
                bsum += os;
            }
            if ((lane & 15) == 0) {
                size_t pidx = (size_t)grow * NBN + blockIdx.x;
                g_pm[pidx] = bmax; g_pi[pidx] = bidx; g_ps[pidx] = bsum;
            }
        }
    } else {
        // ===================== noise role =====================
        const int j = t - 256;   // 0..127
#pragma unroll 1
        for (int it = 0; it < 128; it++) {
            int idx = it * 128 + j;
            int tt = idx & 255, e = idx >> 8;
            int i = e >> 3, ci = e & 7;
            int tty = tt >> 4, ttx = tt & 15;
            int grow = bm + tty * 4 + (i & 3) + (i >> 2) * 64;
            int gcol = bn + ttx * 4 + (ci & 3) + (ci >> 2) * 64;
            uint32_t ctr = (uint32_t)grow * 1024u + (uint32_t)gcol;
            // argmax path: bitwise-exact gumbel g1 = -log(-log(u1))
            uint32_t b1 = tf_bits(k1a, k1b, ctr);
            float u1 = __uint_as_float((b1 >> 9) | 0x3f800000u) - 1.0f;
            float m1 = -__nv_logf(fmaxf(TINYF, u1 + TINYF));
            float g1 = -__nv_logf(m1);
            // softmax path: eg = -1/log(u2), fast mufu log (ws tol 1e-3)
            uint32_t b2 = tf_bits(k2a, k2b, ctr);
            float u2 = __uint_as_float((b2 >> 9) | 0x3f800000u) - 1.0f;
            float eg = -__fdividef(1.0f, __logf(fmaxf(TINYF, u2 + TINYF)));
            nz[idx] = make_float2(g1, eg);
        }
        __syncthreads();   // join; GEMM warps do the epilogue
    }
}

// ---------------------------------------------------------------------------
// Kernel 4: reduce partials per row, normalize ws, gather z_q, indices.
// ---------------------------------------------------------------------------
__global__ void finalize_kernel(const float* __restrict__ cb,
                                float* __restrict__ zq,
                                float* __restrict__ ws,
                                float* __restrict__ idxo) {
    int n = blockIdx.x, t = threadIdx.x;
    __shared__ int   s_best;
    __shared__ float s_inv;
    if (t == 0) {
        float bm = g_pm[(size_t)n * NBN]; int bi = g_pi[(size_t)n * NBN];
        float sum = g_ps[(size_t)n * NBN];
#pragma unroll
        for (int j = 1; j < NBN; j++) {
            float m = g_pm[(size_t)n * NBN + j];
            int   i = g_pi[(size_t)n * NBN + j];
            if (m > bm || (m == bm && i < bi)) { bm = m; bi = i; }
            sum += g_ps[(size_t)n * NBN + j];
        }
        s_best = bi;
        s_inv  = 1.0f / sum;
    }
    __syncthreads();
    int best = s_best; float inv = s_inv;

    float4* wrow = (float4*)(ws + (size_t)n * 1024);
    float4 v = wrow[t];
    v.x *= inv; v.y *= inv; v.z *= inv; v.w *= inv;
    wrow[t] = v;

    if (t < 128) {
        float4 c = *(const float4*)(cb + (size_t)best * D_DIM + t * 4);
        *(float4*)(zq + (size_t)n * D_DIM + t * 4) = c;
    }
    if (t == 0) idxo[n] = (float)best;
}

// ---------------------------------------------------------------------------
extern "C" void kernel_launch(void* const* d_in, const int* in_sizes, int n_in,
                              void* d_out, int out_size) {
    const float* st = (const float*)d_in[0];
    const float* ad = (const float*)d_in[1];
    const float* cb = (const float*)d_in[2];
    int N = in_sizes[0] / D_DIM;     // 32768
    int K = in_sizes[2] / D_DIM;     // 1024

    float* out  = (float*)d_out;
    float* zq   = out;                              // [N, D]
    float* ws   = out + (size_t)N * D_DIM;          // [N, K]
    float* idxo = ws + (size_t)N * K;               // [N, 1]

    // jax.random.key(42) -> (0,42); partitionable fold split
    uint32_t g1a = 0u, g1b = 0u;
    threefry2x32(0u, 42u, g1a, g1b);    // counter 0 -> gk1
    uint32_t g2a = 0u, g2b = 1u;
    threefry2x32(0u, 42u, g2a, g2b);    // counter 1 -> gk2

    cudaFuncSetAttribute(gemm_ws,
        cudaFuncAttributeMaxDynamicSharedMemorySize, 49152 * 4);

    norm_cb_T<<<K / 16, 256>>>(cb);
    combine_T<<<N / 16, 256>>>(st, ad);
    dim3 gg(K / 128, N / 128);
    gemm_ws<<<gg, 384, 49152 * 4>>>(ws, g1a, g1b, g2a, g2b);
    finalize_kernel<<<N, 256>>>(cb, zq, ws, idxo);
}

// round 11
// speedup vs baseline: 1.1777x; 1.1777x over previous
#include <cuda_runtime.h>
#include <cstdint>
#include <cstddef>

#define DI __device__ __forceinline__
static const int D_DIM = 512;
#define MAXN 32768
#define MAXK 1024
#define NBN  8

extern "C" __device__ float __nv_logf(float);

// Scratch (device globals; no allocation allowed)
__device__ float g_xf[(size_t)MAXN * D_DIM * 2];  // 128MB fragment-packed hi/lo A
__device__ float g_cf[(size_t)MAXK * D_DIM * 2];  //   8MB fragment-packed hi/lo B
__device__ float g_pm[(size_t)MAXN * NBN];
__device__ int   g_pi[(size_t)MAXN * NBN];
__device__ float g_ps[(size_t)MAXN * NBN];

// ---------------------------------------------------------------------------
// Threefry-2x32 (exact JAX, partitionable mode)
// ---------------------------------------------------------------------------
__host__ __device__ inline uint32_t rotl32(uint32_t x, int r) {
    return (x << r) | (x >> (32 - r));
}
__host__ __device__ inline void threefry2x32(uint32_t k0, uint32_t k1,
                                             uint32_t& x0, uint32_t& x1) {
    uint32_t k2 = k0 ^ k1 ^ 0x1BD11BDAu;
    x0 += k0; x1 += k1;
#define TFR(r) { x0 += x1; x1 = rotl32(x1, r); x1 ^= x0; }
    TFR(13) TFR(15) TFR(26) TFR(6)
    x0 += k1; x1 += k2 + 1u;
    TFR(17) TFR(29) TFR(16) TFR(24)
    x0 += k2; x1 += k0 + 2u;
    TFR(13) TFR(15) TFR(26) TFR(6)
    x0 += k0; x1 += k1 + 3u;
    TFR(17) TFR(29) TFR(16) TFR(24)
    x0 += k1; x1 += k2 + 4u;
    TFR(13) TFR(15) TFR(26) TFR(6)
    x0 += k2; x1 += k0 + 5u;
#undef TFR
}
DI uint32_t tf_bits(uint32_t k0, uint32_t k1, uint32_t i) {
    uint32_t x0 = 0u, x1 = i;
    threefry2x32(k0, k1, x0, x1);
    return x0 ^ x1;
}
#define TINYF 1.17549435e-38f

// ---------------------------------------------------------------------------
// low-level helpers
// ---------------------------------------------------------------------------
DI uint32_t smem_u32(const void* p) {
    uint32_t a;
    asm("{ .reg .u64 t; cvta.to.shared.u64 t, %1; cvt.u32.u64 %0, t; }"
        : "=r"(a) : "l"(p));
    return a;
}
DI void tf32_split(float x, uint32_t& hi, uint32_t& lo) {
    uint32_t h;
    asm("cvt.rna.tf32.f32 %0, %1;" : "=r"(h) : "f"(x));
    float l = x - __uint_as_float(h);
    uint32_t lr;
    asm("cvt.rna.tf32.f32 %0, %1;" : "=r"(lr) : "f"(l));
    hi = h; lo = lr;
}
DI void cp16(uint32_t saddr, const void* g) {
    asm volatile("cp.async.cg.shared.global [%0], [%1], 16;"
                 :: "r"(saddr), "l"(g) : "memory");
}
#define CP_COMMIT() asm volatile("cp.async.commit_group;" ::: "memory")
#define CP_WAIT0()  asm volatile("cp.async.wait_group 0;" ::: "memory")
DI void lds128(uint32_t* r, uint32_t addr) {
    asm volatile("ld.shared.v4.b32 {%0,%1,%2,%3}, [%4];"
        : "=r"(r[0]), "=r"(r[1]), "=r"(r[2]), "=r"(r[3]) : "r"(addr));
}
DI void barx(int id, int n) {
    asm volatile("bar.sync %0, %1;" :: "r"(id), "r"(n) : "memory");
}
// m16n8k8 tf32 MMA (baseline PTX, drives tensor pipe on sm_103)
DI void mma8(float* d, const uint32_t* a, const uint32_t* b) {
    asm volatile(
        "mma.sync.aligned.m16n8k8.row.col.f32.tf32.tf32.f32 "
        "{%0,%1,%2,%3}, {%4,%5,%6,%7}, {%8,%9}, {%0,%1,%2,%3};"
        : "+f"(d[0]), "+f"(d[1]), "+f"(d[2]), "+f"(d[3])
        : "r"(a[0]), "r"(a[1]), "r"(a[2]), "r"(a[3]), "r"(b[0]), "r"(b[1]));
}

// ---------------------------------------------------------------------------
// Kernel 1: normalize codebook rows, write fragment-packed hi/lo g_cf.
//   (verbatim from the R5 passing kernel)
// ---------------------------------------------------------------------------
__global__ __launch_bounds__(256) void norm_cb_fp(const float* __restrict__ cb) {
    __shared__ float sc[16][516];
    int t = threadIdx.x, lane = t & 31, w = t >> 5;
    int R0 = blockIdx.x * 16;
#pragma unroll
    for (int rr = 0; rr < 2; rr++) {
        int row = 2 * w + rr;
        const float4* rp = (const float4*)(cb + (size_t)(R0 + row) * D_DIM);
        float4 v[4]; float ss = 0.f;
#pragma unroll
        for (int i = 0; i < 4; i++) {
            v[i] = rp[lane + 32 * i];
            ss += v[i].x * v[i].x + v[i].y * v[i].y + v[i].z * v[i].z + v[i].w * v[i].w;
        }
#pragma unroll
        for (int o = 16; o; o >>= 1) ss += __shfl_xor_sync(0xffffffffu, ss, o);
        float inv = 1.0f / fmaxf(sqrtf(ss), 1e-8f);
#pragma unroll
        for (int i = 0; i < 4; i++) {
            float4 q; q.x = v[i].x * inv; q.y = v[i].y * inv;
            q.z = v[i].z * inv; q.w = v[i].w * inv;
            *(float4*)&sc[row][4 * (lane + 32 * i)] = q;
        }
    }
    __syncthreads();
    float* outp = g_cf + (size_t)blockIdx.x * 16384;
#pragma unroll
    for (int q = 0; q < 16; q++) {
        int p = t * 16 + q;
        int nt_l = p >> 11, pp = p & 2047;
        int kt = pp >> 5, ln = pp & 31;
        int nl = nt_l * 8 + (ln >> 2);
        int c  = kt * 8 + (ln & 3);
        uint32_t h0, l0, h1, l1;
        tf32_split(sc[nl][c],     h0, l0);
        tf32_split(sc[nl][c + 4], h1, l1);
        uint4 o; o.x = h0; o.y = h1; o.z = l0; o.w = l1;
        *(uint4*)(outp + (size_t)p * 4) = o;
    }
}

// ---------------------------------------------------------------------------
// Kernel 2: x = 0.5*st/||st|| + 0.5*ad/||ad||, fragment-packed g_xf.
//   (verbatim from R5)
// ---------------------------------------------------------------------------
__global__ __launch_bounds__(256) void combine_fp(const float* __restrict__ st,
                                                  const float* __restrict__ ad) {
    __shared__ float sx[16][516];
    int t = threadIdx.x, lane = t & 31, w = t >> 5;
    int R0 = blockIdx.x * 16;
#pragma unroll
    for (int rr = 0; rr < 2; rr++) {
        int row = 2 * w + rr;
        const float4* sp = (const float4*)(st + (size_t)(R0 + row) * D_DIM);
        const float4* ap = (const float4*)(ad + (size_t)(R0 + row) * D_DIM);
        float4 sv[4], av[4]; float ss = 0.f, aa = 0.f;
#pragma unroll
        for (int i = 0; i < 4; i++) {
            sv[i] = sp[lane + 32 * i];
            av[i] = ap[lane + 32 * i];
            ss += sv[i].x*sv[i].x + sv[i].y*sv[i].y + sv[i].z*sv[i].z + sv[i].w*sv[i].w;
            aa += av[i].x*av[i].x + av[i].y*av[i].y + av[i].z*av[i].z + av[i].w*av[i].w;
        }
#pragma unroll
        for (int o = 16; o; o >>= 1) {
            ss += __shfl_xor_sync(0xffffffffu, ss, o);
            aa += __shfl_xor_sync(0xffffffffu, aa, o);
        }
        float is = 0.5f / fmaxf(sqrtf(ss), 1e-8f);
        float ia = 0.5f / fmaxf(sqrtf(aa), 1e-8f);
#pragma unroll
        for (int i = 0; i < 4; i++) {
            float4 q;
            q.x = sv[i].x * is + av[i].x * ia;
            q.y = sv[i].y * is + av[i].y * ia;
            q.z = sv[i].z * is + av[i].z * ia;
            q.w = sv[i].w * is + av[i].w * ia;
            *(float4*)&sx[row][4 * (lane + 32 * i)] = q;
        }
    }
    __syncthreads();
    float* outp = g_xf + (size_t)blockIdx.x * 16384;
#pragma unroll
    for (int q = 0; q < 8; q++) {
        int p = t * 8 + q;
        int kt = p >> 5, ln = p & 31;
        int g = ln >> 2, c = kt * 8 + (ln & 3);
        uint32_t h[4], l[4];
        tf32_split(sx[g][c],         h[0], l[0]);
        tf32_split(sx[g + 8][c],     h[1], l[1]);
        tf32_split(sx[g][c + 4],     h[2], l[2]);
        tf32_split(sx[g + 8][c + 4], h[3], l[3]);
        uint4 H; H.x = h[0]; H.y = h[1]; H.z = h[2]; H.w = h[3];
        uint4 L; L.x = l[0]; L.y = l[1]; L.z = l[2]; L.w = l[3];
        *(uint4*)(outp + (size_t)p * 8)     = H;
        *(uint4*)(outp + (size_t)p * 8 + 4) = L;
    }
}

// ---------------------------------------------------------------------------
// Kernel 3: R5's 3xTF32 mma.sync GEMM (128x128, BK=32) + 4 NOISE WARPS.
//   t<256: 8 HMMA warps (mainloop verbatim R5, named barrier 1).
//   t>=256: threefry -> nz smem (g1 = -log(-log u1), eg = -1/log u2).
//   Join at __syncthreads; epilogue reads nz (no threefry on critical path).
// SMEM bytes: A [0,32768); B [32768,65536); rm/ri/rs [65536,67072);
//             nz float2[16384] @67072 .. 198144
// ---------------------------------------------------------------------------
#define NZ_OFF 67072
#define SMEMB  198144

__global__ __launch_bounds__(384, 1) void gemm_mma(
        float* __restrict__ ws,
        uint32_t k1a, uint32_t k1b, uint32_t k2a, uint32_t k2b) {
    extern __shared__ char smem[];
    const uint32_t sa = smem_u32(smem);
    const uint32_t sb = sa + 32768;
    float2* nz = (float2*)(smem + NZ_OFF);
    const int t = threadIdx.x, lane = t & 31, wid = t >> 5;
    const int mtb = blockIdx.y * 8, ntb = blockIdx.x * 16;
    const int bm = blockIdx.y * 128, bn = blockIdx.x * 128;

    if (t < 256) {
        // ================= HMMA GEMM role (R5 verbatim) =================
        const int wm = wid >> 1, wn = wid & 1;
        float acc[16][4];
#pragma unroll
        for (int i = 0; i < 16; i++)
#pragma unroll
            for (int j = 0; j < 4; j++) acc[i][j] = 0.f;

        for (int c = 0; c < 16; c++) {
            int kt0 = c * 4;
#pragma unroll
            for (int i = 0; i < 8; i++) {          // A: 2048 x 16B
                int u = t + i * 256;
                int blk = u >> 6, off = u & 63;
                const float* g = g_xf
                    + ((size_t)(mtb + (blk >> 2)) * 64 + kt0 + (blk & 3)) * 256
                    + off * 4;
                cp16(sa + blk * 1024 + off * 16, g);
            }
#pragma unroll
            for (int i = 0; i < 8; i++) {          // B: 2048 x 16B
                int u = t + i * 256;
                int blk = u >> 5, off = u & 31;
                const float* g = g_cf
                    + ((size_t)(ntb + (blk >> 2)) * 64 + kt0 + (blk & 3)) * 128
                    + off * 4;
                cp16(sb + blk * 512 + off * 16, g);
            }
            CP_COMMIT(); CP_WAIT0();
            barx(1, 256);
#pragma unroll
            for (int ktl = 0; ktl < 4; ktl++) {
                uint32_t ah[2][4], al[2][4];
#pragma unroll
                for (int m = 0; m < 2; m++) {
                    uint32_t base = sa + (((wm * 2 + m) * 4 + ktl) * 32 + lane) * 32;
                    lds128(ah[m], base);
                    lds128(al[m], base + 16);
                }
#pragma unroll
                for (int g2 = 0; g2 < 2; g2++) {
                    uint32_t bh[4][2], bl[4][2];
#pragma unroll
                    for (int n4 = 0; n4 < 4; n4++) {
                        uint32_t baddr = sb +
                            (((wn * 8 + g2 * 4 + n4) * 4 + ktl) * 32 + lane) * 16;
                        uint32_t bv[4];
                        lds128(bv, baddr);
                        bh[n4][0] = bv[0]; bh[n4][1] = bv[1];
                        bl[n4][0] = bv[2]; bl[n4][1] = bv[3];
                    }
#pragma unroll
                    for (int m = 0; m < 2; m++)
#pragma unroll
                        for (int n4 = 0; n4 < 4; n4++) {
                            float* A = acc[m * 8 + g2 * 4 + n4];
                            mma8(A, ah[m], bh[n4]);
                            mma8(A, ah[m], bl[n4]);
                            mma8(A, al[m], bh[n4]);
                        }
                }
            }
            barx(1, 256);
        }

        __syncthreads();   // join #1 with noise warps (their STS drained)

        // ---- epilogue: gumbel precomputed in nz ----
        float rmax[4], rsum[4]; int ridx[4];
#pragma unroll
        for (int m = 0; m < 2; m++)
#pragma unroll
        for (int h = 0; h < 2; h++) {
            int e = m * 2 + h;
            int rowloc = wm * 32 + m * 16 + h * 8 + (lane >> 2);
            int colb = wn * 64 + (lane & 3) * 2;       // LOCAL col base
            int grow = bm + rowloc;
            float bmax = -3.4e38f; int bidx = 0; float bsum = 0.f;
            float* wrow = ws + (size_t)grow * 1024 + bn;
#pragma unroll
            for (int n = 0; n < 8; n++) {
                int ccl = colb + n * 8;
                float s0 = acc[m * 8 + n][h * 2];
                float s1 = acc[m * 8 + n][h * 2 + 1];
                float4 nv = *(float4*)&nz[rowloc * 128 + ccl];  // even idx: 16B ✓
                float v1a = s0 + nv.x;
                if (v1a > bmax) { bmax = v1a; bidx = bn + ccl; }
                float v1b = s1 + nv.z;
                if (v1b > bmax) { bmax = v1b; bidx = bn + ccl + 1; }
                float p0 = __expf(s0) * nv.y;
                float p1 = __expf(s1) * nv.w;
                bsum += p0 + p1;
                *(float2*)(wrow + ccl) = make_float2(p0, p1);
            }
#pragma unroll
            for (int o = 1; o <= 2; o <<= 1) {
                float om = __shfl_xor_sync(0xffffffffu, bmax, o);
                int   oi = __shfl_xor_sync(0xffffffffu, bidx, o);
                float os = __shfl_xor_sync(0xffffffffu, bsum, o);
                if (om > bmax || (om == bmax && oi < bidx)) { bmax = om; bidx = oi; }
                bsum += os;
            }
            rmax[e] = bmax; ridx[e] = bidx; rsum[e] = bsum;
        }

        float* rm = (float*)(smem + 65536);
        int*   ri = (int*)  (smem + 65536 + 512);
        float* rs = (float*)(smem + 65536 + 1024);
        if (wn == 1 && (lane & 3) == 0) {
#pragma unroll
            for (int e = 0; e < 4; e++) {
                int rl = wm * 32 + (e >> 1) * 16 + (e & 1) * 8 + (lane >> 2);
                rm[rl] = rmax[e]; ri[rl] = ridx[e]; rs[rl] = rsum[e];
            }
        }
        __syncthreads();   // join #2 (epilogue middle)
        if (wn == 0 && (lane & 3) == 0) {
#pragma unroll
            for (int e = 0; e < 4; e++) {
                int rl = wm * 32 + (e >> 1) * 16 + (e & 1) * 8 + (lane >> 2);
                float om = rm[rl]; int oi = ri[rl]; float os = rs[rl];
                float bmv = rmax[e]; int biv = ridx[e];
                if (om > bmv || (om == bmv && oi < biv)) { bmv = om; biv = oi; }
                size_t pidx = (size_t)(bm + rl) * NBN + blockIdx.x;
                g_pm[pidx] = bmv; g_pi[pidx] = biv; g_ps[pidx] = rsum[e] + os;
            }
        }
    } else {
        // ================= noise role: 16384 elems =================
        const int jj = t - 256;   // 0..127
#pragma unroll 1
        for (int it = 0; it < 128; it++) {
            int idx = it * 128 + jj;
            int row = idx >> 7, col = idx & 127;
            uint32_t ctr = (uint32_t)(bm + row) * 1024u + (uint32_t)(bn + col);
            uint32_t b1 = tf_bits(k1a, k1b, ctr);
            float u1 = __uint_as_float((b1 >> 9) | 0x3f800000u) - 1.0f;
            float m1 = -__nv_logf(fmaxf(TINYF, u1 + TINYF));
            float g1 = -__nv_logf(m1);
            uint32_t b2 = tf_bits(k2a, k2b, ctr);
            float u2 = __uint_as_float((b2 >> 9) | 0x3f800000u) - 1.0f;
            float eg = -__fdividef(1.0f, __nv_logf(fmaxf(TINYF, u2 + TINYF)));
            nz[idx] = make_float2(g1, eg);
        }
        __syncthreads();   // join #1
        __syncthreads();   // join #2 (epilogue middle)
    }
}

// ---------------------------------------------------------------------------
// Kernel 4: reduce partials per row, normalize ws, gather z_q, indices.
// ---------------------------------------------------------------------------
__global__ void finalize_kernel(const float* __restrict__ cb,
                                float* __restrict__ zq,
                                float* __restrict__ ws,
                                float* __restrict__ idxo) {
    int n = blockIdx.x, t = threadIdx.x;
    __shared__ int   s_best;
    __shared__ float s_inv;
    if (t == 0) {
        float bm = g_pm[(size_t)n * NBN]; int bi = g_pi[(size_t)n * NBN];
        float sum = g_ps[(size_t)n * NBN];
#pragma unroll
        for (int j = 1; j < NBN; j++) {
            float m = g_pm[(size_t)n * NBN + j];
            int   i = g_pi[(size_t)n * NBN + j];
            if (m > bm || (m == bm && i < bi)) { bm = m; bi = i; }
            sum += g_ps[(size_t)n * NBN + j];
        }
        s_best = bi;
        s_inv  = 1.0f / sum;
    }
    __syncthreads();
    int best = s_best; float inv = s_inv;

    float4* wrow = (float4*)(ws + (size_t)n * 1024);
    float4 v = wrow[t];
    v.x *= inv; v.y *= inv; v.z *= inv; v.w *= inv;
    wrow[t] = v;

    if (t < 128) {
        float4 c = *(const float4*)(cb + (size_t)best * D_DIM + t * 4);
        *(float4*)(zq + (size_t)n * D_DIM + t * 4) = c;
    }
    if (t == 0) idxo[n] = (float)best;
}

// ---------------------------------------------------------------------------
extern "C" void kernel_launch(void* const* d_in, const int* in_sizes, int n_in,
                              void* d_out, int out_size) {
    const float* st = (const float*)d_in[0];
    const float* ad = (const float*)d_in[1];
    const float* cb = (const float*)d_in[2];
    int N = in_sizes[0] / D_DIM;     // 32768
    int K = in_sizes[2] / D_DIM;     // 1024

    float* out  = (float*)d_out;
    float* zq   = out;                              // [N, D]
    float* ws   = out + (size_t)N * D_DIM;          // [N, K]
    float* idxo = ws + (size_t)N * K;               // [N, 1]

    // jax.random.key(42) -> (0,42); partitionable fold split
    uint32_t g1a = 0u, g1b = 0u;
    threefry2x32(0u, 42u, g1a, g1b);    // counter 0 -> gk1
    uint32_t g2a = 0u, g2b = 1u;
    threefry2x32(0u, 42u, g2a, g2b);    // counter 1 -> gk2

    cudaFuncSetAttribute(gemm_mma,
        cudaFuncAttributeMaxDynamicSharedMemorySize, SMEMB);

    norm_cb_fp<<<K / 16, 256>>>(cb);
    combine_fp<<<N / 16, 256>>>(st, ad);
    dim3 gg(K / 128, N / 128);          // (8, 256)
    gemm_mma<<<gg, 384, SMEMB>>>(ws, g1a, g1b, g2a, g2b);
    finalize_kernel<<<N, 256>>>(cb, zq, ws, idxo);
}